// round 1
// baseline (speedup 1.0000x reference)
#include <cuda_runtime.h>
#include <math.h>

// Problem constants (fixed by reference)
#define BB 4
#define SS 8192
#define DD 512
#define MM (BB * SS)       // 32768 rows
#define LCHUNK 64
#define NCHUNK (SS / LCHUNK)  // 128

// Scratch: raw pre-activation GEMM outputs for the 3 gates (F, I, H), 192 MB.
__device__ float g_gate[3ll * MM * DD];
// Per-chunk affine coefficients and carried-in h.
__device__ float g_chA[BB * NCHUNK * DD];
__device__ float g_chC[BB * NCHUNK * DD];
__device__ float g_hin[BB * NCHUNK * DD];

__device__ __forceinline__ float sigmoidf_(float x) {
    return 1.0f / (1.0f + __expf(-x));
}
// g(x) = relu(x)+0.5 for x>=0 ; exp(-softplus(-x)) = sigmoid(x) for x<0
__device__ __forceinline__ float gfun_(float x) {
    return (x >= 0.0f) ? (x + 0.5f) : sigmoidf_(x);
}

// ---------------------------------------------------------------------------
// GEMM: out[gate][m][n] = sum_k x[m][k] * W[k][n] + bias[n]
// 128x128 block tile, 8x8 per thread, TK=8, double-buffered smem.
// grid = (DD/128, MM/128, 3), block = 256
// ---------------------------------------------------------------------------
__global__ __launch_bounds__(256) void gemm3_kernel(
    const float* __restrict__ x,
    const float* __restrict__ Wf, const float* __restrict__ bf,
    const float* __restrict__ Wi, const float* __restrict__ bi,
    const float* __restrict__ Wh, const float* __restrict__ bh)
{
    const int gate = blockIdx.z;
    const float* __restrict__ W    = (gate == 0) ? Wf : ((gate == 1) ? Wi : Wh);
    const float* __restrict__ bias = (gate == 0) ? bf : ((gate == 1) ? bi : bh);
    float* __restrict__ out = g_gate + (size_t)gate * MM * DD;

    const int m0 = blockIdx.y * 128;
    const int n0 = blockIdx.x * 128;
    const int tid = threadIdx.x;

    __shared__ __align__(16) float xs[2][8][128];  // [buf][k][m] (x tile, transposed)
    __shared__ __align__(16) float ws[2][8][128];  // [buf][k][n]

    // Load-index mapping (one float4 per thread per tile)
    const int xr = tid >> 1;          // 0..127 : row within x tile
    const int xk = (tid & 1) * 4;     // 0 or 4 : k offset
    const int wr = tid >> 5;          // 0..7   : k row within W tile
    const int wc = (tid & 31) * 4;    // 0..124 : col within W tile

    const int ty = tid >> 4;          // 0..15
    const int tx = tid & 15;          // 0..15

    float acc[8][8];
#pragma unroll
    for (int i = 0; i < 8; i++)
#pragma unroll
        for (int j = 0; j < 8; j++) acc[i][j] = 0.0f;

    // Prologue: load k-tile 0
    {
        float4 xv = *(const float4*)(x + (size_t)(m0 + xr) * DD + xk);
        xs[0][xk + 0][xr] = xv.x;
        xs[0][xk + 1][xr] = xv.y;
        xs[0][xk + 2][xr] = xv.z;
        xs[0][xk + 3][xr] = xv.w;
        float4 wv = *(const float4*)(W + (size_t)wr * DD + n0 + wc);
        *(float4*)&ws[0][wr][wc] = wv;
    }
    __syncthreads();

    const int nk = DD / 8;  // 64 k-tiles
    int buf = 0;
#pragma unroll 1
    for (int t = 0; t < nk; t++) {
        float4 xv, wv;
        const bool has_next = (t + 1) < nk;
        if (has_next) {
            const int kk = (t + 1) * 8;
            xv = *(const float4*)(x + (size_t)(m0 + xr) * DD + kk + xk);
            wv = *(const float4*)(W + (size_t)(kk + wr) * DD + n0 + wc);
        }

        // Compute current k-tile from smem[buf]
#pragma unroll
        for (int k = 0; k < 8; k++) {
            float a[8], b[8];
            float4 a0 = *(float4*)&xs[buf][k][ty * 8];
            float4 a1 = *(float4*)&xs[buf][k][ty * 8 + 4];
            float4 b0 = *(float4*)&ws[buf][k][tx * 8];
            float4 b1 = *(float4*)&ws[buf][k][tx * 8 + 4];
            a[0] = a0.x; a[1] = a0.y; a[2] = a0.z; a[3] = a0.w;
            a[4] = a1.x; a[5] = a1.y; a[6] = a1.z; a[7] = a1.w;
            b[0] = b0.x; b[1] = b0.y; b[2] = b0.z; b[3] = b0.w;
            b[4] = b1.x; b[5] = b1.y; b[6] = b1.z; b[7] = b1.w;
#pragma unroll
            for (int i = 0; i < 8; i++)
#pragma unroll
                for (int j = 0; j < 8; j++)
                    acc[i][j] = fmaf(a[i], b[j], acc[i][j]);
        }

        if (has_next) {
            const int nb = buf ^ 1;
            xs[nb][xk + 0][xr] = xv.x;
            xs[nb][xk + 1][xr] = xv.y;
            xs[nb][xk + 2][xr] = xv.z;
            xs[nb][xk + 3][xr] = xv.w;
            *(float4*)&ws[nb][wr][wc] = wv;
            __syncthreads();
            buf = nb;
        }
    }

    // Epilogue: add bias, store
    float bb[8];
#pragma unroll
    for (int j = 0; j < 8; j++) bb[j] = bias[n0 + tx * 8 + j];

#pragma unroll
    for (int i = 0; i < 8; i++) {
        const int m = m0 + ty * 8 + i;
        float* orow = out + (size_t)m * DD + n0 + tx * 8;
        float4 c0, c1;
        c0.x = acc[i][0] + bb[0]; c0.y = acc[i][1] + bb[1];
        c0.z = acc[i][2] + bb[2]; c0.w = acc[i][3] + bb[3];
        c1.x = acc[i][4] + bb[4]; c1.y = acc[i][5] + bb[5];
        c1.z = acc[i][6] + bb[6]; c1.w = acc[i][7] + bb[7];
        *(float4*)(orow) = c0;
        *(float4*)(orow + 4) = c1;
    }
}

// ---------------------------------------------------------------------------
// Scan pass 1: per-chunk affine reduction. grid=(NCHUNK, BB), block=DD
//   h_out = A * h_in + C over the chunk
// ---------------------------------------------------------------------------
__global__ __launch_bounds__(DD) void scan_chunks_kernel()
{
    const int b = blockIdx.y;
    const int c = blockIdx.x;
    const int d = threadIdx.x;

    const float* __restrict__ F = g_gate;
    const float* __restrict__ I = g_gate + (size_t)MM * DD;
    const float* __restrict__ H = g_gate + 2ll * MM * DD;

    size_t idx = ((size_t)(b * SS + c * LCHUNK)) * DD + d;
    float A = 1.0f, C = 0.0f;
#pragma unroll 4
    for (int s = 0; s < LCHUNK; s++) {
        float f = sigmoidf_(F[idx]);
        float v = sigmoidf_(I[idx]) * gfun_(H[idx]);
        A *= f;
        C = fmaf(f, C, v);
        idx += DD;
    }
    const int o = (b * NCHUNK + c) * DD + d;
    g_chA[o] = A;
    g_chC[o] = C;
}

// ---------------------------------------------------------------------------
// Scan pass 2: serial carry across chunks. grid=BB, block=DD
// ---------------------------------------------------------------------------
__global__ __launch_bounds__(DD) void scan_carry_kernel(const float* __restrict__ pre_h)
{
    const int b = blockIdx.x;
    const int d = threadIdx.x;
    float h = gfun_(pre_h[b * DD + d]);  // h_0 = exp(log_g(pre_h))
#pragma unroll 4
    for (int c = 0; c < NCHUNK; c++) {
        const int o = (b * NCHUNK + c) * DD + d;
        g_hin[o] = h;
        h = fmaf(g_chA[o], h, g_chC[o]);
    }
}

// ---------------------------------------------------------------------------
// Scan pass 3: replay chunks with correct h_in, write output.
// grid=(NCHUNK, BB), block=DD
// ---------------------------------------------------------------------------
__global__ __launch_bounds__(DD) void scan_apply_kernel(float* __restrict__ out)
{
    const int b = blockIdx.y;
    const int c = blockIdx.x;
    const int d = threadIdx.x;

    const float* __restrict__ F = g_gate;
    const float* __restrict__ I = g_gate + (size_t)MM * DD;
    const float* __restrict__ H = g_gate + 2ll * MM * DD;

    float h = g_hin[(b * NCHUNK + c) * DD + d];
    size_t idx = ((size_t)(b * SS + c * LCHUNK)) * DD + d;
#pragma unroll 4
    for (int s = 0; s < LCHUNK; s++) {
        float f = sigmoidf_(F[idx]);
        float v = sigmoidf_(I[idx]) * gfun_(H[idx]);
        h = fmaf(f, h, v);
        out[idx] = h;
        idx += DD;
    }
}

// ---------------------------------------------------------------------------
extern "C" void kernel_launch(void* const* d_in, const int* in_sizes, int n_in,
                              void* d_out, int out_size)
{
    const float* x     = (const float*)d_in[0];
    const float* pre_h = (const float*)d_in[1];
    const float* Wf    = (const float*)d_in[2];
    const float* bf    = (const float*)d_in[3];
    const float* Wi    = (const float*)d_in[4];
    const float* bi    = (const float*)d_in[5];
    const float* Wh    = (const float*)d_in[6];
    const float* bh    = (const float*)d_in[7];
    float* out = (float*)d_out;

    dim3 gg(DD / 128, MM / 128, 3);
    gemm3_kernel<<<gg, 256>>>(x, Wf, bf, Wi, bi, Wh, bh);

    scan_chunks_kernel<<<dim3(NCHUNK, BB), DD>>>();
    scan_carry_kernel<<<BB, DD>>>(pre_h);
    scan_apply_kernel<<<dim3(NCHUNK, BB), DD>>>(out);
}

// round 3
// speedup vs baseline: 2.2742x; 2.2742x over previous
#include <cuda_runtime.h>
#include <cuda_fp16.h>
#include <cstdint>

// ---------------------------------------------------------------------------
// Problem constants
// ---------------------------------------------------------------------------
#define BB 4
#define SS 8192
#define DD 512
#define MM (BB * SS)          // 32768 rows
#define NG 1536               // fused output cols: [F | I | H]
#define KA 1024               // stored A k-extent: [x_hi | x_lo]
#define KB 1536               // B k-extent: [W_hi ; W_lo ; W_hi]

#define TM 128                // CTA tile M
#define TN 128                // CTA tile N
#define KC 64                 // K chunk (128 bytes fp16 per row)
#define NCH (KB / KC)         // 24 chunks
#define NSTAGE 3

#define LCHUNK 64
#define NCHUNK (SS / LCHUNK)  // 128

// ---------------------------------------------------------------------------
// Device scratch
// ---------------------------------------------------------------------------
__device__ __align__(256) __half g_A[(size_t)MM * KA];   // 64 MB
__device__ __align__(256) __half g_B[(size_t)NG * KB];   // 4.7 MB
__device__ float g_bias[NG];
__device__ float g_act[(size_t)MM * NG];                 // 192 MB: f, i, g(h~)
__device__ float g_chA[BB * NCHUNK * DD];
__device__ float g_chC[BB * NCHUNK * DD];
__device__ float g_hin[BB * NCHUNK * DD];

// ---------------------------------------------------------------------------
// Helpers
// ---------------------------------------------------------------------------
__device__ __forceinline__ float sigmoidf_(float x) { return 1.0f / (1.0f + __expf(-x)); }
__device__ __forceinline__ float gfun_(float x)     { return (x >= 0.0f) ? (x + 0.5f) : sigmoidf_(x); }

__device__ __forceinline__ uint32_t smem_u32(const void* p) {
    uint32_t a;
    asm("{ .reg .u64 t; cvta.to.shared.u64 t, %1; cvt.u32.u64 %0, t; }" : "=r"(a) : "l"(p));
    return a;
}
__device__ __forceinline__ void cpasync16(uint32_t dst, const void* src) {
    asm volatile("cp.async.cg.shared.global [%0], [%1], 16;" :: "r"(dst), "l"(src));
}
__device__ __forceinline__ void ldsm4(uint32_t addr, uint32_t& r0, uint32_t& r1,
                                      uint32_t& r2, uint32_t& r3) {
    asm volatile("ldmatrix.sync.aligned.m8n8.x4.shared.b16 {%0,%1,%2,%3}, [%4];"
                 : "=r"(r0), "=r"(r1), "=r"(r2), "=r"(r3) : "r"(addr));
}
__device__ __forceinline__ void mma16816(float* c, const uint32_t* a, const uint32_t* b) {
    asm volatile(
        "mma.sync.aligned.m16n8k16.row.col.f32.f16.f16.f32 "
        "{%0,%1,%2,%3}, {%4,%5,%6,%7}, {%8,%9}, {%0,%1,%2,%3};"
        : "+f"(c[0]), "+f"(c[1]), "+f"(c[2]), "+f"(c[3])
        : "r"(a[0]), "r"(a[1]), "r"(a[2]), "r"(a[3]), "r"(b[0]), "r"(b[1]));
}

// ---------------------------------------------------------------------------
// Prep A: x (fp32, row 512) -> [hi | lo] fp16 limbs (row 1024)
// ---------------------------------------------------------------------------
__global__ __launch_bounds__(256) void prep_A(const float* __restrict__ x)
{
    const int m = blockIdx.x;
    const float* xr = x + (size_t)m * DD;
    __half* ar = g_A + (size_t)m * KA;
#pragma unroll
    for (int i = 0; i < 2; i++) {
        int k = threadIdx.x + i * 256;
        float v = xr[k];
        __half h = __float2half_rn(v);
        __half l = __float2half_rn(v - __half2float(h));
        ar[k]       = h;
        ar[512 + k] = l;
    }
}

// ---------------------------------------------------------------------------
// Prep B: per output col n, row = [W_hi(512) | W_lo(512) | W_hi(512)]
// ---------------------------------------------------------------------------
__global__ __launch_bounds__(512) void prep_B(
    const float* __restrict__ Wf, const float* __restrict__ bf,
    const float* __restrict__ Wi, const float* __restrict__ bi,
    const float* __restrict__ Wh, const float* __restrict__ bh)
{
    const int n = blockIdx.x;               // 0..1535
    const int g = n >> 9, nl = n & 511;
    const float* W    = (g == 0) ? Wf : ((g == 1) ? Wi : Wh);
    const float* bias = (g == 0) ? bf : ((g == 1) ? bi : bh);
    __half* br = g_B + (size_t)n * KB;
    for (int k = threadIdx.x; k < DD; k += blockDim.x) {
        float v = W[(size_t)k * DD + nl];
        __half h = __float2half_rn(v);
        __half l = __float2half_rn(v - __half2float(h));
        br[k]        = h;
        br[512 + k]  = l;
        br[1024 + k] = h;
    }
    if (threadIdx.x == 0) g_bias[n] = bias[nl];
}

// ---------------------------------------------------------------------------
// HMMA GEMM: g_act[m][n] = act( sum_k A'[m,k] B'[n,k] + bias[n] )
// CTA 128x128, warp 32x64, KC=64 chunks, 3-stage cp.async pipeline.
// grid = (NG/TN, MM/TM), block = 256
// ---------------------------------------------------------------------------
__global__ __launch_bounds__(256, 2) void gemm_tc()
{
    extern __shared__ __align__(128) char smem_raw[];
    const uint32_t sbase = smem_u32(smem_raw);

    const int tid  = threadIdx.x;
    const int lane = tid & 31;
    const int wid  = tid >> 5;
    const int wm   = wid >> 1;            // 0..3  (m)
    const int wn   = wid & 1;             // 0..1  (n)
    const int m0 = blockIdx.y * TM;
    const int n0 = blockIdx.x * TN;
    const int gate = n0 >> 9;             // whole CTA in one gate

    const int quad = lane >> 3;
    const int lrow = lane & 7;

    const __half* gA = g_A + (size_t)m0 * KA;
    const __half* gB = g_B + (size_t)n0 * KB;

    // loader: A tile 128x64 fp16 (16KB, swizzled) + B tile 128x64 (16KB)
    auto load_chunk = [&](int c, int s) {
        const uint32_t aB = sbase + (uint32_t)s * 32768u;
        const uint32_t bB = aB + 16384u;
        // A k-offset: chunks 0-7 -> hi, 8-15 -> hi again, 16-23 -> lo
        const int akoff = ((c < 16) ? (c & 7) : (c - 8)) * KC;
        const int bkoff = c * KC;
#pragma unroll
        for (int j = 0; j < 4; j++) {
            const int flat = tid + j * 256;       // 0..1023
            const int r  = flat >> 3;             // row 0..127
            const int sg = flat & 7;              // 16B segment 0..7
            const uint32_t sw = ((uint32_t)(sg ^ (r & 7))) << 4;
            cpasync16(aB + (uint32_t)r * 128u + sw, gA + (size_t)r * KA + akoff + sg * 8);
            cpasync16(bB + (uint32_t)r * 128u + sw, gB + (size_t)r * KB + bkoff + sg * 8);
        }
        asm volatile("cp.async.commit_group;" ::: "memory");
    };

    float acc[2][8][4];
#pragma unroll
    for (int i = 0; i < 2; i++)
#pragma unroll
        for (int j = 0; j < 8; j++)
#pragma unroll
            for (int q = 0; q < 4; q++) acc[i][j][q] = 0.0f;

    load_chunk(0, 0);
    load_chunk(1, 1);

#pragma unroll 1
    for (int c = 0; c < NCH; c++) {
        const int s = c % 3;
        asm volatile("cp.async.wait_group 1;" ::: "memory");
        __syncthreads();
        if (c + 2 < NCH) load_chunk(c + 2, (c + 2) % 3);
        else             asm volatile("cp.async.commit_group;" ::: "memory");

        const uint32_t aB = sbase + (uint32_t)s * 32768u;
        const uint32_t bB = aB + 16384u;

#pragma unroll
        for (int ks = 0; ks < 4; ks++) {
            uint32_t afr[2][4];
#pragma unroll
            for (int mt = 0; mt < 2; mt++) {
                const int row = wm * 32 + mt * 16 + (quad & 1) * 8 + lrow;
                const int seg = (ks * 2) + (quad >> 1);
                const uint32_t addr = aB + (uint32_t)row * 128u +
                                      ((uint32_t)(seg ^ (row & 7)) << 4);
                ldsm4(addr, afr[mt][0], afr[mt][1], afr[mt][2], afr[mt][3]);
            }
            uint32_t bfr[8][2];
#pragma unroll
            for (int np = 0; np < 4; np++) {
                const int nrow = wn * 64 + np * 16 + (quad >> 1) * 8 + lrow;
                const int seg = (ks * 2) + (quad & 1);
                const uint32_t addr = bB + (uint32_t)nrow * 128u +
                                      ((uint32_t)(seg ^ (nrow & 7)) << 4);
                ldsm4(addr, bfr[np * 2][0], bfr[np * 2][1],
                            bfr[np * 2 + 1][0], bfr[np * 2 + 1][1]);
            }
#pragma unroll
            for (int mt = 0; mt < 2; mt++)
#pragma unroll
                for (int nt = 0; nt < 8; nt++)
                    mma16816(acc[mt][nt], afr[mt], bfr[nt]);
        }
    }
    __syncthreads();

    // Epilogue: bias + activation + store fp32
#pragma unroll
    for (int mt = 0; mt < 2; mt++) {
        const int mr = m0 + wm * 32 + mt * 16 + (lane >> 2);
#pragma unroll
        for (int nt = 0; nt < 8; nt++) {
            const int n = n0 + wn * 64 + nt * 8 + (lane & 3) * 2;
            const float bx = __ldg(&g_bias[n]);
            const float by = __ldg(&g_bias[n + 1]);
            float x0 = acc[mt][nt][0] + bx;
            float x1 = acc[mt][nt][1] + by;
            float x2 = acc[mt][nt][2] + bx;
            float x3 = acc[mt][nt][3] + by;
            float2 v0, v1;
            if (gate < 2) {
                v0.x = sigmoidf_(x0); v0.y = sigmoidf_(x1);
                v1.x = sigmoidf_(x2); v1.y = sigmoidf_(x3);
            } else {
                v0.x = gfun_(x0); v0.y = gfun_(x1);
                v1.x = gfun_(x2); v1.y = gfun_(x3);
            }
            *(float2*)(g_act + (size_t)mr * NG + n)       = v0;
            *(float2*)(g_act + (size_t)(mr + 8) * NG + n) = v1;
        }
    }
}

// ---------------------------------------------------------------------------
// Scan pass 1: per-chunk affine reduction
// ---------------------------------------------------------------------------
__global__ __launch_bounds__(DD) void scan_chunks_kernel()
{
    const int b = blockIdx.y, c = blockIdx.x, d = threadIdx.x;
    const float* p = g_act + (size_t)(b * SS + c * LCHUNK) * NG + d;
    float A = 1.0f, C = 0.0f;
#pragma unroll 4
    for (int s = 0; s < LCHUNK; s++) {
        float f = p[0];
        float v = p[512] * p[1024];
        A *= f;
        C = fmaf(f, C, v);
        p += NG;
    }
    const int o = (b * NCHUNK + c) * DD + d;
    g_chA[o] = A;
    g_chC[o] = C;
}

// ---------------------------------------------------------------------------
// Scan pass 2: serial carry across chunks
// ---------------------------------------------------------------------------
__global__ __launch_bounds__(DD) void scan_carry_kernel(const float* __restrict__ pre_h)
{
    const int b = blockIdx.x, d = threadIdx.x;
    float h = gfun_(pre_h[b * DD + d]);
#pragma unroll 4
    for (int c = 0; c < NCHUNK; c++) {
        const int o = (b * NCHUNK + c) * DD + d;
        g_hin[o] = h;
        h = fmaf(g_chA[o], h, g_chC[o]);
    }
}

// ---------------------------------------------------------------------------
// Scan pass 3: replay chunks, write output
// ---------------------------------------------------------------------------
__global__ __launch_bounds__(DD) void scan_apply_kernel(float* __restrict__ out)
{
    const int b = blockIdx.y, c = blockIdx.x, d = threadIdx.x;
    float h = g_hin[(b * NCHUNK + c) * DD + d];
    const float* p = g_act + (size_t)(b * SS + c * LCHUNK) * NG + d;
    float* po = out + (size_t)(b * SS + c * LCHUNK) * DD + d;
#pragma unroll 4
    for (int s = 0; s < LCHUNK; s++) {
        float f = p[0];
        float v = p[512] * p[1024];
        h = fmaf(f, h, v);
        *po = h;
        p += NG;
        po += DD;
    }
}

// ---------------------------------------------------------------------------
extern "C" void kernel_launch(void* const* d_in, const int* in_sizes, int n_in,
                              void* d_out, int out_size)
{
    const float* x     = (const float*)d_in[0];
    const float* pre_h = (const float*)d_in[1];
    const float* Wf    = (const float*)d_in[2];
    const float* bf    = (const float*)d_in[3];
    const float* Wi    = (const float*)d_in[4];
    const float* bi    = (const float*)d_in[5];
    const float* Wh    = (const float*)d_in[6];
    const float* bh    = (const float*)d_in[7];
    float* out = (float*)d_out;

    static bool attr_set = false;
    if (!attr_set) {
        cudaFuncSetAttribute(gemm_tc, cudaFuncAttributeMaxDynamicSharedMemorySize,
                             NSTAGE * 32768);
        attr_set = true;
    }

    prep_A<<<MM, 256>>>(x);
    prep_B<<<NG, 512>>>(Wf, bf, Wi, bi, Wh, bh);

    gemm_tc<<<dim3(NG / TN, MM / TM), 256, NSTAGE * 32768>>>();

    scan_chunks_kernel<<<dim3(NCHUNK, BB), DD>>>();
    scan_carry_kernel<<<BB, DD>>>(pre_h);
    scan_apply_kernel<<<dim3(NCHUNK, BB), DD>>>(out);
}

// round 4
// speedup vs baseline: 3.0747x; 1.3520x over previous
#include <cuda_runtime.h>
#include <cuda_fp16.h>
#include <cstdint>

// ---------------------------------------------------------------------------
// Problem constants
// ---------------------------------------------------------------------------
#define BB 4
#define SS 8192
#define DD 512
#define MM (BB * SS)          // 32768 rows
#define NG 1536               // fused GEMM cols: [F(512) | interleaved I/H (1024)]
#define KA 1024               // A k-extent: [x_hi | x_lo]
#define KB 1024               // B k-extent: [W_hi | W_hi]

#define TM 128                // CTA tile M
#define TN 128                // CTA tile N
#define KC 64                 // K chunk (128 bytes fp16 per row)
#define NCH (KA / KC)         // 16 chunks
#define NSTAGE 3

#define LCHUNK 64
#define NCHUNK (SS / LCHUNK)  // 128

// ---------------------------------------------------------------------------
// Device scratch
// ---------------------------------------------------------------------------
__device__ __align__(256) __half g_A[(size_t)MM * KA];   // 64 MB
__device__ __align__(256) __half g_B[(size_t)NG * KB];   // 3 MB
__device__ float g_bias[NG];
__device__ float g_f[(size_t)MM * DD];                   // 64 MB: f = sigmoid(kF)
__device__ float g_v[(size_t)MM * DD];                   // 64 MB: v = i * g(h~)
__device__ float g_chA[BB * NCHUNK * DD];
__device__ float g_chC[BB * NCHUNK * DD];
__device__ float g_hin[BB * NCHUNK * DD];

// ---------------------------------------------------------------------------
// Helpers
// ---------------------------------------------------------------------------
__device__ __forceinline__ float sigmoidf_(float x) { return 1.0f / (1.0f + __expf(-x)); }
__device__ __forceinline__ float gfun_(float x)     { return (x >= 0.0f) ? (x + 0.5f) : sigmoidf_(x); }

__device__ __forceinline__ uint32_t smem_u32(const void* p) {
    uint32_t a;
    asm("{ .reg .u64 t; cvta.to.shared.u64 t, %1; cvt.u32.u64 %0, t; }" : "=r"(a) : "l"(p));
    return a;
}
__device__ __forceinline__ void cpasync16(uint32_t dst, const void* src) {
    asm volatile("cp.async.cg.shared.global [%0], [%1], 16;" :: "r"(dst), "l"(src));
}
__device__ __forceinline__ void ldsm4(uint32_t addr, uint32_t& r0, uint32_t& r1,
                                      uint32_t& r2, uint32_t& r3) {
    asm volatile("ldmatrix.sync.aligned.m8n8.x4.shared.b16 {%0,%1,%2,%3}, [%4];"
                 : "=r"(r0), "=r"(r1), "=r"(r2), "=r"(r3) : "r"(addr));
}
__device__ __forceinline__ void mma16816(float* c, const uint32_t* a, const uint32_t* b) {
    asm volatile(
        "mma.sync.aligned.m16n8k16.row.col.f32.f16.f16.f32 "
        "{%0,%1,%2,%3}, {%4,%5,%6,%7}, {%8,%9}, {%0,%1,%2,%3};"
        : "+f"(c[0]), "+f"(c[1]), "+f"(c[2]), "+f"(c[3])
        : "r"(a[0]), "r"(a[1]), "r"(a[2]), "r"(a[3]), "r"(b[0]), "r"(b[1]));
}

// ---------------------------------------------------------------------------
// Prep A: x (fp32, row 512) -> [hi | lo] fp16 limbs (row 1024)
// ---------------------------------------------------------------------------
__global__ __launch_bounds__(256) void prep_A(const float* __restrict__ x)
{
    const int m = blockIdx.x;
    const float* xr = x + (size_t)m * DD;
    __half* ar = g_A + (size_t)m * KA;
#pragma unroll
    for (int i = 0; i < 2; i++) {
        int k = threadIdx.x + i * 256;
        float v = xr[k];
        __half h = __float2half_rn(v);
        __half l = __float2half_rn(v - __half2float(h));
        ar[k]       = h;
        ar[512 + k] = l;
    }
}

// ---------------------------------------------------------------------------
// Prep B: permuted columns.
//   n' <  512 : gate F, d = n'
//   n' >= 512 : q = n'-512, d = q>>1, gate = (q&1) ? H : I
// Row n' = [W_hi(512) | W_hi(512)]  (duplicated so both A limbs hit W_hi)
// ---------------------------------------------------------------------------
__global__ __launch_bounds__(512) void prep_B(
    const float* __restrict__ Wf, const float* __restrict__ bf,
    const float* __restrict__ Wi, const float* __restrict__ bi,
    const float* __restrict__ Wh, const float* __restrict__ bh)
{
    const int n = blockIdx.x;               // 0..1535 (permuted col id)
    const float* W;
    const float* bias;
    int d;
    if (n < 512) { W = Wf; bias = bf; d = n; }
    else {
        const int q = n - 512;
        d = q >> 1;
        if (q & 1) { W = Wh; bias = bh; }
        else       { W = Wi; bias = bi; }
    }
    __half* br = g_B + (size_t)n * KB;
    for (int k = threadIdx.x; k < DD; k += blockDim.x) {
        __half h = __float2half_rn(W[(size_t)k * DD + d]);
        br[k]       = h;
        br[512 + k] = h;
    }
    if (threadIdx.x == 0) g_bias[n] = bias[d];
}

// ---------------------------------------------------------------------------
// HMMA GEMM + fused activation epilogue.
// CTA 128x128, warp 32x64, KC=64 chunks, 3-stage cp.async pipeline.
// grid = (NG/TN, MM/TM), block = 256
// ---------------------------------------------------------------------------
__global__ __launch_bounds__(256, 2) void gemm_tc()
{
    extern __shared__ __align__(128) char smem_raw[];
    const uint32_t sbase = smem_u32(smem_raw);

    const int tid  = threadIdx.x;
    const int lane = tid & 31;
    const int wid  = tid >> 5;
    const int wm   = wid >> 1;            // 0..3  (m)
    const int wn   = wid & 1;             // 0..1  (n)
    const int m0 = blockIdx.y * TM;
    const int n0 = blockIdx.x * TN;

    const int quad = lane >> 3;
    const int lrow = lane & 7;

    const __half* gA = g_A + (size_t)m0 * KA;
    const __half* gB = g_B + (size_t)n0 * KB;

    auto load_chunk = [&](int c, int s) {
        const uint32_t aB = sbase + (uint32_t)s * 32768u;
        const uint32_t bB = aB + 16384u;
        const int koff = c * KC;
#pragma unroll
        for (int j = 0; j < 4; j++) {
            const int flat = tid + j * 256;       // 0..1023
            const int r  = flat >> 3;             // row 0..127
            const int sg = flat & 7;              // 16B segment 0..7
            const uint32_t sw = ((uint32_t)(sg ^ (r & 7))) << 4;
            cpasync16(aB + (uint32_t)r * 128u + sw, gA + (size_t)r * KA + koff + sg * 8);
            cpasync16(bB + (uint32_t)r * 128u + sw, gB + (size_t)r * KB + koff + sg * 8);
        }
        asm volatile("cp.async.commit_group;" ::: "memory");
    };

    float acc[2][8][4];
#pragma unroll
    for (int i = 0; i < 2; i++)
#pragma unroll
        for (int j = 0; j < 8; j++)
#pragma unroll
            for (int q = 0; q < 4; q++) acc[i][j][q] = 0.0f;

    load_chunk(0, 0);
    load_chunk(1, 1);

#pragma unroll 1
    for (int c = 0; c < NCH; c++) {
        const int s = c % 3;
        asm volatile("cp.async.wait_group 1;" ::: "memory");
        __syncthreads();
        if (c + 2 < NCH) load_chunk(c + 2, (c + 2) % 3);
        else             asm volatile("cp.async.commit_group;" ::: "memory");

        const uint32_t aB = sbase + (uint32_t)s * 32768u;
        const uint32_t bB = aB + 16384u;

#pragma unroll
        for (int ks = 0; ks < 4; ks++) {
            uint32_t afr[2][4];
#pragma unroll
            for (int mt = 0; mt < 2; mt++) {
                const int row = wm * 32 + mt * 16 + (quad & 1) * 8 + lrow;
                const int seg = (ks * 2) + (quad >> 1);
                const uint32_t addr = aB + (uint32_t)row * 128u +
                                      ((uint32_t)(seg ^ (row & 7)) << 4);
                ldsm4(addr, afr[mt][0], afr[mt][1], afr[mt][2], afr[mt][3]);
            }
            uint32_t bfr[8][2];
#pragma unroll
            for (int np = 0; np < 4; np++) {
                const int nrow = wn * 64 + np * 16 + (quad >> 1) * 8 + lrow;
                const int seg = (ks * 2) + (quad & 1);
                const uint32_t addr = bB + (uint32_t)nrow * 128u +
                                      ((uint32_t)(seg ^ (nrow & 7)) << 4);
                ldsm4(addr, bfr[np * 2][0], bfr[np * 2][1],
                            bfr[np * 2 + 1][0], bfr[np * 2 + 1][1]);
            }
#pragma unroll
            for (int mt = 0; mt < 2; mt++)
#pragma unroll
                for (int nt = 0; nt < 8; nt++)
                    mma16816(acc[mt][nt], afr[mt], bfr[nt]);
        }
    }
    __syncthreads();

    if (n0 < 512) {
        // F gate: f = sigmoid(k + b), write float2 pairs directly
#pragma unroll
        for (int mt = 0; mt < 2; mt++) {
            const int mr = m0 + wm * 32 + mt * 16 + (lane >> 2);
#pragma unroll
            for (int nt = 0; nt < 8; nt++) {
                const int n = n0 + wn * 64 + nt * 8 + (lane & 3) * 2;
                const float bx = __ldg(&g_bias[n]);
                const float by = __ldg(&g_bias[n + 1]);
                float2 v0, v1;
                v0.x = sigmoidf_(acc[mt][nt][0] + bx);
                v0.y = sigmoidf_(acc[mt][nt][1] + by);
                v1.x = sigmoidf_(acc[mt][nt][2] + bx);
                v1.y = sigmoidf_(acc[mt][nt][3] + by);
                *(float2*)(g_f + (size_t)mr * DD + n)       = v0;
                *(float2*)(g_f + (size_t)(mr + 8) * DD + n) = v1;
            }
        }
    } else {
        // I/H interleaved: fragment cols (2j, 2j+1) = (I_d, H_d)
        // v = sigmoid(kI + bI) * g(kH + bH). Stage in smem, coalesced store.
        float* vbuf = (float*)smem_raw;     // [128][68] padded, 34816 B
        const int dloc_base = wn * 32;      // local d offset for this warp
#pragma unroll
        for (int mt = 0; mt < 2; mt++) {
            const int rloc = wm * 32 + mt * 16 + (lane >> 2);
#pragma unroll
            for (int nt = 0; nt < 8; nt++) {
                const int n = n0 + wn * 64 + nt * 8 + (lane & 3) * 2;
                const float bi_ = __ldg(&g_bias[n]);
                const float bh_ = __ldg(&g_bias[n + 1]);
                const int dloc = dloc_base + nt * 4 + (lane & 3);
                vbuf[rloc * 68 + dloc] =
                    sigmoidf_(acc[mt][nt][0] + bi_) * gfun_(acc[mt][nt][1] + bh_);
                vbuf[(rloc + 8) * 68 + dloc] =
                    sigmoidf_(acc[mt][nt][2] + bi_) * gfun_(acc[mt][nt][3] + bh_);
            }
        }
        __syncthreads();
        const int dbase = (n0 - 512) >> 1;   // global d of local col 0
#pragma unroll
        for (int j = 0; j < 8; j++) {
            const int flat = tid + j * 256;  // 0..2047 float4 units
            const int r  = flat >> 4;        // row 0..127
            const int f4 = flat & 15;        // 0..15
            float4 val = *(float4*)(vbuf + r * 68 + f4 * 4);
            *(float4*)(g_v + (size_t)(m0 + r) * DD + dbase + f4 * 4) = val;
        }
    }
}

// ---------------------------------------------------------------------------
// Scan pass 1: per-chunk affine reduction
// ---------------------------------------------------------------------------
__global__ __launch_bounds__(DD) void scan_chunks_kernel()
{
    const int b = blockIdx.y, c = blockIdx.x, d = threadIdx.x;
    size_t idx = (size_t)(b * SS + c * LCHUNK) * DD + d;
    float A = 1.0f, C = 0.0f;
#pragma unroll 4
    for (int s = 0; s < LCHUNK; s++) {
        float f = g_f[idx];
        float v = g_v[idx];
        A *= f;
        C = fmaf(f, C, v);
        idx += DD;
    }
    const int o = (b * NCHUNK + c) * DD + d;
    g_chA[o] = A;
    g_chC[o] = C;
}

// ---------------------------------------------------------------------------
// Scan pass 2: serial carry across chunks
// ---------------------------------------------------------------------------
__global__ __launch_bounds__(DD) void scan_carry_kernel(const float* __restrict__ pre_h)
{
    const int b = blockIdx.x, d = threadIdx.x;
    float h = gfun_(pre_h[b * DD + d]);
#pragma unroll 4
    for (int c = 0; c < NCHUNK; c++) {
        const int o = (b * NCHUNK + c) * DD + d;
        g_hin[o] = h;
        h = fmaf(g_chA[o], h, g_chC[o]);
    }
}

// ---------------------------------------------------------------------------
// Scan pass 3: replay chunks, write output
// ---------------------------------------------------------------------------
__global__ __launch_bounds__(DD) void scan_apply_kernel(float* __restrict__ out)
{
    const int b = blockIdx.y, c = blockIdx.x, d = threadIdx.x;
    float h = g_hin[(b * NCHUNK + c) * DD + d];
    size_t idx = (size_t)(b * SS + c * LCHUNK) * DD + d;
#pragma unroll 4
    for (int s = 0; s < LCHUNK; s++) {
        float f = g_f[idx];
        float v = g_v[idx];
        h = fmaf(f, h, v);
        out[idx] = h;
        idx += DD;
    }
}

// ---------------------------------------------------------------------------
extern "C" void kernel_launch(void* const* d_in, const int* in_sizes, int n_in,
                              void* d_out, int out_size)
{
    const float* x     = (const float*)d_in[0];
    const float* pre_h = (const float*)d_in[1];
    const float* Wf    = (const float*)d_in[2];
    const float* bf    = (const float*)d_in[3];
    const float* Wi    = (const float*)d_in[4];
    const float* bi    = (const float*)d_in[5];
    const float* Wh    = (const float*)d_in[6];
    const float* bh    = (const float*)d_in[7];
    float* out = (float*)d_out;

    static bool attr_set = false;
    if (!attr_set) {
        cudaFuncSetAttribute(gemm_tc, cudaFuncAttributeMaxDynamicSharedMemorySize,
                             NSTAGE * 32768);
        attr_set = true;
    }

    prep_A<<<MM, 256>>>(x);
    prep_B<<<NG, 512>>>(Wf, bf, Wi, bi, Wh, bh);

    gemm_tc<<<dim3(NG / TN, MM / TM), 256, NSTAGE * 32768>>>();

    scan_chunks_kernel<<<dim3(NCHUNK, BB), DD>>>();
    scan_carry_kernel<<<BB, DD>>>(pre_h);
    scan_apply_kernel<<<dim3(NCHUNK, BB), DD>>>(out);
}

// round 5
// speedup vs baseline: 4.6387x; 1.5086x over previous
#include <cuda_runtime.h>
#include <cuda_fp16.h>
#include <cstdint>

// ---------------------------------------------------------------------------
// Problem constants
// ---------------------------------------------------------------------------
#define BB 4
#define SS 8192
#define DD 512
#define MM (BB * SS)          // 32768 rows
#define NG 1536               // fused GEMM cols: [F(512) | interleaved I/H (1024)]
#define KA 512                // A k-extent: fp16(x)
#define KB 512                // B k-extent: fp16(W)

#define TM 128                // CTA tile M
#define TN 128                // CTA tile N
#define KC 64                 // K chunk (128 bytes fp16 per row)
#define NCH (KA / KC)         // 8 chunks
#define NSTAGE 3

#define LCHUNK 64
#define NCHUNK (SS / LCHUNK)  // 128

// ---------------------------------------------------------------------------
// Device scratch
// ---------------------------------------------------------------------------
__device__ __align__(256) __half g_A[(size_t)MM * KA];   // 32 MB
__device__ __align__(256) __half g_B[(size_t)NG * KB];   // 1.5 MB
__device__ float g_bias[NG];
__device__ __align__(256) __half g_f[(size_t)MM * DD];   // 32 MB
__device__ __align__(256) __half g_v[(size_t)MM * DD];   // 32 MB
__device__ float g_chA[BB * NCHUNK * DD];
__device__ float g_chC[BB * NCHUNK * DD];
__device__ float g_hin[BB * NCHUNK * DD];

// ---------------------------------------------------------------------------
// Helpers
// ---------------------------------------------------------------------------
__device__ __forceinline__ float sigmoidf_(float x) { return 1.0f / (1.0f + __expf(-x)); }
__device__ __forceinline__ float gfun_(float x)     { return (x >= 0.0f) ? (x + 0.5f) : sigmoidf_(x); }

__device__ __forceinline__ uint32_t smem_u32(const void* p) {
    uint32_t a;
    asm("{ .reg .u64 t; cvta.to.shared.u64 t, %1; cvt.u32.u64 %0, t; }" : "=r"(a) : "l"(p));
    return a;
}
__device__ __forceinline__ void cpasync16(uint32_t dst, const void* src) {
    asm volatile("cp.async.cg.shared.global [%0], [%1], 16;" :: "r"(dst), "l"(src));
}
__device__ __forceinline__ void ldsm4(uint32_t addr, uint32_t& r0, uint32_t& r1,
                                      uint32_t& r2, uint32_t& r3) {
    asm volatile("ldmatrix.sync.aligned.m8n8.x4.shared.b16 {%0,%1,%2,%3}, [%4];"
                 : "=r"(r0), "=r"(r1), "=r"(r2), "=r"(r3) : "r"(addr));
}
__device__ __forceinline__ void mma16816(float* c, const uint32_t* a, const uint32_t* b) {
    asm volatile(
        "mma.sync.aligned.m16n8k16.row.col.f32.f16.f16.f32 "
        "{%0,%1,%2,%3}, {%4,%5,%6,%7}, {%8,%9}, {%0,%1,%2,%3};"
        : "+f"(c[0]), "+f"(c[1]), "+f"(c[2]), "+f"(c[3])
        : "r"(a[0]), "r"(a[1]), "r"(a[2]), "r"(a[3]), "r"(b[0]), "r"(b[1]));
}

// ---------------------------------------------------------------------------
// Prep A: streaming fp32 -> fp16 cast (A = fp16(x), identical layout)
// grid = 8192, block = 256, 8 elems/thread
// ---------------------------------------------------------------------------
__global__ __launch_bounds__(256) void prep_A(const float* __restrict__ x)
{
    const size_t i = ((size_t)blockIdx.x * 256 + threadIdx.x) * 8;
    float4 v0 = *(const float4*)(x + i);
    float4 v1 = *(const float4*)(x + i + 4);
    __half2 h[4];
    h[0] = __floats2half2_rn(v0.x, v0.y);
    h[1] = __floats2half2_rn(v0.z, v0.w);
    h[2] = __floats2half2_rn(v1.x, v1.y);
    h[3] = __floats2half2_rn(v1.z, v1.w);
    *(uint4*)(g_A + i) = *(uint4*)h;
}

// ---------------------------------------------------------------------------
// Prep B: permuted columns.
//   n <  512 : gate F, d = n
//   n >= 512 : q = n-512, d = q>>1, gate = (q&1) ? H : I
// ---------------------------------------------------------------------------
__global__ __launch_bounds__(512) void prep_B(
    const float* __restrict__ Wf, const float* __restrict__ bf,
    const float* __restrict__ Wi, const float* __restrict__ bi,
    const float* __restrict__ Wh, const float* __restrict__ bh)
{
    const int n = blockIdx.x;               // 0..1535 (permuted col id)
    const float* W;
    const float* bias;
    int d;
    if (n < 512) { W = Wf; bias = bf; d = n; }
    else {
        const int q = n - 512;
        d = q >> 1;
        if (q & 1) { W = Wh; bias = bh; }
        else       { W = Wi; bias = bi; }
    }
    __half* br = g_B + (size_t)n * KB;
    for (int k = threadIdx.x; k < DD; k += blockDim.x)
        br[k] = __float2half_rn(W[(size_t)k * DD + d]);
    if (threadIdx.x == 0) g_bias[n] = bias[d];
}

// ---------------------------------------------------------------------------
// HMMA GEMM + fused activation epilogue (fp16 outputs).
// CTA 128x128, warp 32x64, KC=64 chunks, 3-stage cp.async pipeline.
// grid = (NG/TN, MM/TM), block = 256
// ---------------------------------------------------------------------------
__global__ __launch_bounds__(256, 2) void gemm_tc()
{
    extern __shared__ __align__(128) char smem_raw[];
    const uint32_t sbase = smem_u32(smem_raw);

    const int tid  = threadIdx.x;
    const int lane = tid & 31;
    const int wid  = tid >> 5;
    const int wm   = wid >> 1;            // 0..3  (m)
    const int wn   = wid & 1;             // 0..1  (n)
    const int m0 = blockIdx.y * TM;
    const int n0 = blockIdx.x * TN;

    const int quad = lane >> 3;
    const int lrow = lane & 7;

    const __half* gA = g_A + (size_t)m0 * KA;
    const __half* gB = g_B + (size_t)n0 * KB;

    auto load_chunk = [&](int c, int s) {
        const uint32_t aB = sbase + (uint32_t)s * 32768u;
        const uint32_t bB = aB + 16384u;
        const int koff = c * KC;
#pragma unroll
        for (int j = 0; j < 4; j++) {
            const int flat = tid + j * 256;       // 0..1023
            const int r  = flat >> 3;             // row 0..127
            const int sg = flat & 7;              // 16B segment 0..7
            const uint32_t sw = ((uint32_t)(sg ^ (r & 7))) << 4;
            cpasync16(aB + (uint32_t)r * 128u + sw, gA + (size_t)r * KA + koff + sg * 8);
            cpasync16(bB + (uint32_t)r * 128u + sw, gB + (size_t)r * KB + koff + sg * 8);
        }
        asm volatile("cp.async.commit_group;" ::: "memory");
    };

    float acc[2][8][4];
#pragma unroll
    for (int i = 0; i < 2; i++)
#pragma unroll
        for (int j = 0; j < 8; j++)
#pragma unroll
            for (int q = 0; q < 4; q++) acc[i][j][q] = 0.0f;

    load_chunk(0, 0);
    load_chunk(1, 1);

#pragma unroll 1
    for (int c = 0; c < NCH; c++) {
        const int s = c % 3;
        asm volatile("cp.async.wait_group 1;" ::: "memory");
        __syncthreads();
        if (c + 2 < NCH) load_chunk(c + 2, (c + 2) % 3);
        else             asm volatile("cp.async.commit_group;" ::: "memory");

        const uint32_t aB = sbase + (uint32_t)s * 32768u;
        const uint32_t bB = aB + 16384u;

#pragma unroll
        for (int ks = 0; ks < 4; ks++) {
            uint32_t afr[2][4];
#pragma unroll
            for (int mt = 0; mt < 2; mt++) {
                const int row = wm * 32 + mt * 16 + (quad & 1) * 8 + lrow;
                const int seg = (ks * 2) + (quad >> 1);
                const uint32_t addr = aB + (uint32_t)row * 128u +
                                      ((uint32_t)(seg ^ (row & 7)) << 4);
                ldsm4(addr, afr[mt][0], afr[mt][1], afr[mt][2], afr[mt][3]);
            }
            uint32_t bfr[8][2];
#pragma unroll
            for (int np = 0; np < 4; np++) {
                const int nrow = wn * 64 + np * 16 + (quad >> 1) * 8 + lrow;
                const int seg = (ks * 2) + (quad & 1);
                const uint32_t addr = bB + (uint32_t)nrow * 128u +
                                      ((uint32_t)(seg ^ (nrow & 7)) << 4);
                ldsm4(addr, bfr[np * 2][0], bfr[np * 2][1],
                            bfr[np * 2 + 1][0], bfr[np * 2 + 1][1]);
            }
#pragma unroll
            for (int mt = 0; mt < 2; mt++)
#pragma unroll
                for (int nt = 0; nt < 8; nt++)
                    mma16816(acc[mt][nt], afr[mt], bfr[nt]);
        }
    }
    __syncthreads();

    if (n0 < 512) {
        // F gate: f = sigmoid(k + b), store half2 pairs
#pragma unroll
        for (int mt = 0; mt < 2; mt++) {
            const int mr = m0 + wm * 32 + mt * 16 + (lane >> 2);
#pragma unroll
            for (int nt = 0; nt < 8; nt++) {
                const int n = n0 + wn * 64 + nt * 8 + (lane & 3) * 2;
                const float bx = __ldg(&g_bias[n]);
                const float by = __ldg(&g_bias[n + 1]);
                __half2 p0 = __floats2half2_rn(sigmoidf_(acc[mt][nt][0] + bx),
                                               sigmoidf_(acc[mt][nt][1] + by));
                __half2 p1 = __floats2half2_rn(sigmoidf_(acc[mt][nt][2] + bx),
                                               sigmoidf_(acc[mt][nt][3] + by));
                *(__half2*)(g_f + (size_t)mr * DD + n)       = p0;
                *(__half2*)(g_f + (size_t)(mr + 8) * DD + n) = p1;
            }
        }
    } else {
        // I/H interleaved: fragment cols (2j, 2j+1) = (I_d, H_d)
        // v = sigmoid(kI + bI) * g(kH + bH). Stage fp32 in smem, store fp16.
        float* vbuf = (float*)smem_raw;     // [128][68] padded, 34816 B
        const int dloc_base = wn * 32;
#pragma unroll
        for (int mt = 0; mt < 2; mt++) {
            const int rloc = wm * 32 + mt * 16 + (lane >> 2);
#pragma unroll
            for (int nt = 0; nt < 8; nt++) {
                const int n = n0 + wn * 64 + nt * 8 + (lane & 3) * 2;
                const float bi_ = __ldg(&g_bias[n]);
                const float bh_ = __ldg(&g_bias[n + 1]);
                const int dloc = dloc_base + nt * 4 + (lane & 3);
                vbuf[rloc * 68 + dloc] =
                    sigmoidf_(acc[mt][nt][0] + bi_) * gfun_(acc[mt][nt][1] + bh_);
                vbuf[(rloc + 8) * 68 + dloc] =
                    sigmoidf_(acc[mt][nt][2] + bi_) * gfun_(acc[mt][nt][3] + bh_);
            }
        }
        __syncthreads();
        const int dbase = (n0 - 512) >> 1;   // global d of local col 0
#pragma unroll
        for (int j = 0; j < 8; j++) {
            const int flat = tid + j * 256;  // 0..2047 float4 units
            const int r  = flat >> 4;        // row 0..127
            const int f4 = flat & 15;        // 0..15
            float4 val = *(float4*)(vbuf + r * 68 + f4 * 4);
            __half2 h01 = __floats2half2_rn(val.x, val.y);
            __half2 h23 = __floats2half2_rn(val.z, val.w);
            uint2 pk;
            pk.x = *(uint32_t*)&h01;
            pk.y = *(uint32_t*)&h23;
            *(uint2*)(g_v + (size_t)(m0 + r) * DD + dbase + f4 * 4) = pk;
        }
    }
}

// ---------------------------------------------------------------------------
// Scan pass 1: per-chunk affine reduction. block=256 (2 channels/thread)
// ---------------------------------------------------------------------------
__global__ __launch_bounds__(256) void scan_chunks_kernel()
{
    const int b = blockIdx.y, c = blockIdx.x, t = threadIdx.x;
    const __half2* F = (const __half2*)g_f;
    const __half2* V = (const __half2*)g_v;
    size_t idx = (size_t)(b * SS + c * LCHUNK) * (DD / 2) + t;
    float2 A = {1.0f, 1.0f}, C = {0.0f, 0.0f};
#pragma unroll 4
    for (int s = 0; s < LCHUNK; s++) {
        float2 f = __half22float2(F[idx]);
        float2 v = __half22float2(V[idx]);
        A.x *= f.x;  A.y *= f.y;
        C.x = fmaf(f.x, C.x, v.x);
        C.y = fmaf(f.y, C.y, v.y);
        idx += DD / 2;
    }
    const int o = (b * NCHUNK + c) * DD + 2 * t;
    *(float2*)(g_chA + o) = A;
    *(float2*)(g_chC + o) = C;
}

// ---------------------------------------------------------------------------
// Scan pass 2: serial carry across chunks. block=256
// ---------------------------------------------------------------------------
__global__ __launch_bounds__(256) void scan_carry_kernel(const float* __restrict__ pre_h)
{
    const int b = blockIdx.x, t = threadIdx.x;
    float2 h;
    h.x = gfun_(pre_h[b * DD + 2 * t]);
    h.y = gfun_(pre_h[b * DD + 2 * t + 1]);
#pragma unroll 4
    for (int c = 0; c < NCHUNK; c++) {
        const int o = (b * NCHUNK + c) * DD + 2 * t;
        *(float2*)(g_hin + o) = h;
        float2 A = *(const float2*)(g_chA + o);
        float2 C = *(const float2*)(g_chC + o);
        h.x = fmaf(A.x, h.x, C.x);
        h.y = fmaf(A.y, h.y, C.y);
    }
}

// ---------------------------------------------------------------------------
// Scan pass 3: replay chunks, write fp32 output. block=256
// ---------------------------------------------------------------------------
__global__ __launch_bounds__(256) void scan_apply_kernel(float* __restrict__ out)
{
    const int b = blockIdx.y, c = blockIdx.x, t = threadIdx.x;
    const __half2* F = (const __half2*)g_f;
    const __half2* V = (const __half2*)g_v;
    float2 h = *(const float2*)(g_hin + (b * NCHUNK + c) * DD + 2 * t);
    size_t idx = (size_t)(b * SS + c * LCHUNK) * (DD / 2) + t;
#pragma unroll 4
    for (int s = 0; s < LCHUNK; s++) {
        float2 f = __half22float2(F[idx]);
        float2 v = __half22float2(V[idx]);
        h.x = fmaf(f.x, h.x, v.x);
        h.y = fmaf(f.y, h.y, v.y);
        *(float2*)(out + idx * 2) = h;
        idx += DD / 2;
    }
}

// ---------------------------------------------------------------------------
extern "C" void kernel_launch(void* const* d_in, const int* in_sizes, int n_in,
                              void* d_out, int out_size)
{
    const float* x     = (const float*)d_in[0];
    const float* pre_h = (const float*)d_in[1];
    const float* Wf    = (const float*)d_in[2];
    const float* bf    = (const float*)d_in[3];
    const float* Wi    = (const float*)d_in[4];
    const float* bi    = (const float*)d_in[5];
    const float* Wh    = (const float*)d_in[6];
    const float* bh    = (const float*)d_in[7];
    float* out = (float*)d_out;

    static bool attr_set = false;
    if (!attr_set) {
        cudaFuncSetAttribute(gemm_tc, cudaFuncAttributeMaxDynamicSharedMemorySize,
                             NSTAGE * 32768);
        attr_set = true;
    }

    prep_A<<<(MM * DD) / (256 * 8), 256>>>(x);
    prep_B<<<NG, 512>>>(Wf, bf, Wi, bi, Wh, bh);

    gemm_tc<<<dim3(NG / TN, MM / TM), 256, NSTAGE * 32768>>>();

    scan_chunks_kernel<<<dim3(NCHUNK, BB), 256>>>();
    scan_carry_kernel<<<BB, 256>>>(pre_h);
    scan_apply_kernel<<<dim3(NCHUNK, BB), 256>>>(out);
}